// round 4
// baseline (speedup 1.0000x reference)
#include <cuda_runtime.h>
#include <cuda_bf16.h>
#include <cstdint>

// Problem constants (match reference_code)
#define NN   100000
#define C_IN  128
#define C_HID 128
#define C_OUT 64
#define EE   1600000

// -------- device scratch (static allocation; no cudaMalloc allowed) --------
__device__ float g_dinv[NN];                       // deg -> rsqrt(deg)
__device__ float g_norm[EE];
__device__ float g_h1[(size_t)NN * C_HID];         // x @ W1
__device__ float g_a1[(size_t)NN * C_HID];         // agg1 (+b1, relu)
__device__ float g_h2[(size_t)NN * C_OUT];         // a1 @ W2
__device__ float g_out[(size_t)NN * C_OUT];        // layer-2 accumulator (device-owned)

// ---------------------------------------------------------------------------
__global__ void k_init_deg() {
    int i = blockIdx.x * blockDim.x + threadIdx.x;
    if (i < NN) g_dinv[i] = 1.0f;                  // self-loop
}

// edge_index is int32 (JAX default: int64 request silently becomes int32)
__global__ void k_count(const int* __restrict__ ei) {
    int e = blockIdx.x * blockDim.x + threadIdx.x;
    if (e >= EE) return;
    int d = ei[EE + e];
    atomicAdd(&g_dinv[d], 1.0f);
}

__global__ void k_rsqrt() {
    int i = blockIdx.x * blockDim.x + threadIdx.x;
    if (i < NN) g_dinv[i] = rsqrtf(g_dinv[i]);
}

__global__ void k_norm(const int* __restrict__ ei) {
    int e = blockIdx.x * blockDim.x + threadIdx.x;
    if (e >= EE) return;
    g_norm[e] = g_dinv[ei[e]] * g_dinv[ei[EE + e]];
}

// ---------------------------------------------------------------------------
// GEMM1: g_h1[N,128] = x[N,128] @ W1[128,128]
__global__ void k_gemm1(const float* __restrict__ A, const float* __restrict__ W) {
    __shared__ float sW[64 * 128];
    const int c4  = (threadIdx.x & 31) * 4;
    const int rt  = threadIdx.x >> 5;
    const size_t row0 = (size_t)blockIdx.x * 32 + rt * 4;

    float4 acc[4];
    #pragma unroll
    for (int r = 0; r < 4; r++) acc[r] = make_float4(0.f, 0.f, 0.f, 0.f);

    for (int kk = 0; kk < 128; kk += 64) {
        const float4* Wv  = (const float4*)(W + (size_t)kk * 128);
        float4*       sWv = (float4*)sW;
        #pragma unroll
        for (int i = threadIdx.x; i < 2048; i += 256) sWv[i] = Wv[i];
        __syncthreads();

        #pragma unroll
        for (int k4 = 0; k4 < 16; k4++) {
            float4 xv[4];
            #pragma unroll
            for (int r = 0; r < 4; r++)
                xv[r] = *(const float4*)(A + (row0 + r) * 128 + kk + k4 * 4);
            #pragma unroll
            for (int kq = 0; kq < 4; kq++) {
                float4 w = *(const float4*)&sW[(k4 * 4 + kq) * 128 + c4];
                #pragma unroll
                for (int r = 0; r < 4; r++) {
                    float xs = (kq == 0) ? xv[r].x : (kq == 1) ? xv[r].y
                             : (kq == 2) ? xv[r].z : xv[r].w;
                    acc[r].x += xs * w.x;
                    acc[r].y += xs * w.y;
                    acc[r].z += xs * w.z;
                    acc[r].w += xs * w.w;
                }
            }
        }
        __syncthreads();
    }
    #pragma unroll
    for (int r = 0; r < 4; r++)
        *(float4*)(g_h1 + (row0 + r) * 128 + c4) = acc[r];
}

// GEMM2: g_h2[N,64] = g_a1[N,128] @ W2[128,64]
__global__ void k_gemm2(const float* __restrict__ W2) {
    __shared__ float sW[128 * 64];
    const int c4 = (threadIdx.x & 15) * 4;
    const int rt = threadIdx.x >> 4;
    const size_t row0 = (size_t)blockIdx.x * 64 + rt * 4;

    const float4* Wv  = (const float4*)W2;
    float4*       sWv = (float4*)sW;
    #pragma unroll
    for (int i = threadIdx.x; i < 2048; i += 256) sWv[i] = Wv[i];
    __syncthreads();

    if (row0 >= NN) return;

    float4 acc[4];
    #pragma unroll
    for (int r = 0; r < 4; r++) acc[r] = make_float4(0.f, 0.f, 0.f, 0.f);

    #pragma unroll
    for (int k4 = 0; k4 < 32; k4++) {
        float4 xv[4];
        #pragma unroll
        for (int r = 0; r < 4; r++)
            xv[r] = *(const float4*)(g_a1 + (row0 + r) * 128 + k4 * 4);
        #pragma unroll
        for (int kq = 0; kq < 4; kq++) {
            float4 w = *(const float4*)&sW[(k4 * 4 + kq) * 64 + c4];
            #pragma unroll
            for (int r = 0; r < 4; r++) {
                float xs = (kq == 0) ? xv[r].x : (kq == 1) ? xv[r].y
                         : (kq == 2) ? xv[r].z : xv[r].w;
                acc[r].x += xs * w.x;
                acc[r].y += xs * w.y;
                acc[r].z += xs * w.z;
                acc[r].w += xs * w.w;
            }
        }
    }
    #pragma unroll
    for (int r = 0; r < 4; r++)
        *(float4*)(g_h2 + (row0 + r) * 64 + c4) = acc[r];
}

// ---------------------------------------------------------------------------
// a1 init: a1 = h1 * dinv^2 + b1   (self-loop + bias folded in before scatter)
__global__ void k_init_a1(const float* __restrict__ b1) {
    size_t t = (size_t)blockIdx.x * blockDim.x + threadIdx.x;
    if (t >= (size_t)NN * 32) return;
    size_t i  = t >> 5;
    int    c4 = (int)(t & 31) * 4;
    float di = g_dinv[i];
    float s  = di * di;
    float4 h = *(const float4*)(g_h1 + i * 128 + c4);
    float4 b = *(const float4*)(b1 + c4);
    float4 o = make_float4(h.x * s + b.x, h.y * s + b.y, h.z * s + b.z, h.w * s + b.w);
    *(float4*)(g_a1 + i * 128 + c4) = o;
}

// Layer-1 edge scatter: warp per edge, scalar float atomics to device-owned g_a1.
__global__ void k_scatter1(const int* __restrict__ ei) {
    int t = blockIdx.x * blockDim.x + threadIdx.x;
    int e = t >> 5;
    if (e >= EE) return;
    int j4 = (t & 31) * 4;
    int s = ei[e];
    int d = ei[EE + e];
    float w = g_norm[e];
    float4 v = *(const float4*)(g_h1 + (size_t)s * 128 + j4);
    float* dst = g_a1 + (size_t)d * 128 + j4;
    atomicAdd(dst + 0, v.x * w);
    atomicAdd(dst + 1, v.y * w);
    atomicAdd(dst + 2, v.z * w);
    atomicAdd(dst + 3, v.w * w);
}

__global__ void k_relu() {
    size_t t = (size_t)blockIdx.x * blockDim.x + threadIdx.x;
    if (t >= (size_t)NN * 32) return;
    float4* p = (float4*)g_a1 + t;
    float4 v = *p;
    v.x = fmaxf(v.x, 0.f); v.y = fmaxf(v.y, 0.f);
    v.z = fmaxf(v.z, 0.f); v.w = fmaxf(v.w, 0.f);
    *p = v;
}

// out init into device-owned accumulator: g_out = h2 * dinv^2 + b2
__global__ void k_init_out(const float* __restrict__ b2) {
    size_t t = (size_t)blockIdx.x * blockDim.x + threadIdx.x;
    if (t >= (size_t)NN * 16) return;
    size_t i  = t >> 4;
    int    c4 = (int)(t & 15) * 4;
    float di = g_dinv[i];
    float s  = di * di;
    float4 h = *(const float4*)(g_h2 + i * 64 + c4);
    float4 b = *(const float4*)(b2 + c4);
    float4 o = make_float4(h.x * s + b.x, h.y * s + b.y, h.z * s + b.z, h.w * s + b.w);
    *(float4*)(g_out + i * 64 + c4) = o;
}

// Layer-2 edge scatter: 16 lanes per edge, scalar atomics to device-owned g_out.
__global__ void k_scatter2(const int* __restrict__ ei) {
    int t = blockIdx.x * blockDim.x + threadIdx.x;
    int e = t >> 4;
    if (e >= EE) return;
    int j4 = (t & 15) * 4;
    int s = ei[e];
    int d = ei[EE + e];
    float w = g_norm[e];
    float4 v = *(const float4*)(g_h2 + (size_t)s * 64 + j4);
    float* dst = g_out + (size_t)d * 64 + j4;
    atomicAdd(dst + 0, v.x * w);
    atomicAdd(dst + 1, v.y * w);
    atomicAdd(dst + 2, v.z * w);
    atomicAdd(dst + 3, v.w * w);
}

// Final: plain coalesced stores into harness's d_out (no atomics on d_out).
__global__ void k_copy_out(float* __restrict__ out) {
    size_t t = (size_t)blockIdx.x * blockDim.x + threadIdx.x;
    if (t >= (size_t)NN * 16) return;
    ((float4*)out)[t] = ((const float4*)g_out)[t];
}

// ---------------------------------------------------------------------------
extern "C" void kernel_launch(void* const* d_in, const int* in_sizes, int n_in,
                              void* d_out, int out_size) {
    const float* x  = (const float*)d_in[0];
    const int*   ei = (const int*)d_in[1];     // int32! (JAX x64 disabled)
    const float* W1 = (const float*)d_in[2];
    const float* b1 = (const float*)d_in[3];
    const float* W2 = (const float*)d_in[4];
    const float* b2 = (const float*)d_in[5];
    float* out = (float*)d_out;

    const int T = 256;

    // degrees + edge preprocessing
    k_init_deg<<<(NN + T - 1) / T, T>>>();
    k_count<<<(EE + T - 1) / T, T>>>(ei);
    k_rsqrt<<<(NN + T - 1) / T, T>>>();
    k_norm<<<(EE + T - 1) / T, T>>>(ei);

    // layer 1
    k_gemm1<<<NN / 32, T>>>(x, W1);                       // 100000 % 32 == 0
    k_init_a1<<<((size_t)NN * 32 + T - 1) / T, T>>>(b1);
    k_scatter1<<<((size_t)EE * 32 + T - 1) / T, T>>>(ei);
    k_relu<<<((size_t)NN * 32 + T - 1) / T, T>>>();

    // layer 2
    k_gemm2<<<(NN + 63) / 64, T>>>(W2);
    k_init_out<<<((size_t)NN * 16 + T - 1) / T, T>>>(b2);
    k_scatter2<<<((size_t)EE * 16 + T - 1) / T, T>>>(ei);
    k_copy_out<<<((size_t)NN * 16 + T - 1) / T, T>>>(out);
}

// round 5
// speedup vs baseline: 1.7364x; 1.7364x over previous
#include <cuda_runtime.h>
#include <cuda_bf16.h>
#include <cstdint>

// Problem constants (match reference_code)
#define NN   100000
#define C_IN  128
#define C_HID 128
#define C_OUT 64
#define EE   1600000

// -------- device scratch (static allocation; no cudaMalloc allowed) --------
__device__ float g_dinv[NN];                       // deg -> rsqrt(deg)
__device__ float g_norm[EE];
__device__ float g_h1[(size_t)NN * C_HID];         // x @ W1
__device__ float g_a1[(size_t)NN * C_HID];         // agg1 (self-loop+bias init, scatter target)
__device__ float g_h2[(size_t)NN * C_OUT];         // relu(a1) @ W2
__device__ float g_out[(size_t)NN * C_OUT];        // layer-2 accumulator (device-owned)

// ---------------------------------------------------------------------------
__global__ void k_init_deg() {
    int i = blockIdx.x * blockDim.x + threadIdx.x;
    if (i < NN) g_dinv[i] = 1.0f;                  // self-loop
}

// edge_index is int32 (JAX default: int64 request silently becomes int32)
__global__ void k_count(const int* __restrict__ ei) {
    int e = blockIdx.x * blockDim.x + threadIdx.x;
    if (e >= EE) return;
    atomicAdd(&g_dinv[ei[EE + e]], 1.0f);
}

__global__ void k_rsqrt() {
    int i = blockIdx.x * blockDim.x + threadIdx.x;
    if (i < NN) g_dinv[i] = rsqrtf(g_dinv[i]);
}

__global__ void k_norm(const int* __restrict__ ei) {
    int e = blockIdx.x * blockDim.x + threadIdx.x;
    if (e >= EE) return;
    g_norm[e] = g_dinv[ei[e]] * g_dinv[ei[EE + e]];
}

// ---------------------------------------------------------------------------
// GEMM1: h1 = x @ W1; epilogue also writes a1 = h1*dinv^2 + b1 (self-loop+bias)
__global__ void k_gemm1(const float* __restrict__ A, const float* __restrict__ W,
                        const float* __restrict__ b1) {
    __shared__ float sW[64 * 128];
    const int c4  = (threadIdx.x & 31) * 4;
    const int rt  = threadIdx.x >> 5;
    const size_t row0 = (size_t)blockIdx.x * 32 + rt * 4;

    float4 acc[4];
    #pragma unroll
    for (int r = 0; r < 4; r++) acc[r] = make_float4(0.f, 0.f, 0.f, 0.f);

    for (int kk = 0; kk < 128; kk += 64) {
        const float4* Wv  = (const float4*)(W + (size_t)kk * 128);
        float4*       sWv = (float4*)sW;
        #pragma unroll
        for (int i = threadIdx.x; i < 2048; i += 256) sWv[i] = Wv[i];
        __syncthreads();

        #pragma unroll
        for (int k4 = 0; k4 < 16; k4++) {
            float4 xv[4];
            #pragma unroll
            for (int r = 0; r < 4; r++)
                xv[r] = *(const float4*)(A + (row0 + r) * 128 + kk + k4 * 4);
            #pragma unroll
            for (int kq = 0; kq < 4; kq++) {
                float4 w = *(const float4*)&sW[(k4 * 4 + kq) * 128 + c4];
                #pragma unroll
                for (int r = 0; r < 4; r++) {
                    float xs = (kq == 0) ? xv[r].x : (kq == 1) ? xv[r].y
                             : (kq == 2) ? xv[r].z : xv[r].w;
                    acc[r].x += xs * w.x;
                    acc[r].y += xs * w.y;
                    acc[r].z += xs * w.z;
                    acc[r].w += xs * w.w;
                }
            }
        }
        __syncthreads();
    }

    float4 b = *(const float4*)(b1 + c4);
    #pragma unroll
    for (int r = 0; r < 4; r++) {
        size_t row = row0 + r;
        *(float4*)(g_h1 + row * 128 + c4) = acc[r];
        float di = g_dinv[row];
        float s  = di * di;
        float4 o = make_float4(acc[r].x * s + b.x, acc[r].y * s + b.y,
                               acc[r].z * s + b.z, acc[r].w * s + b.w);
        *(float4*)(g_a1 + row * 128 + c4) = o;
    }
}

// GEMM2: h2 = relu(a1) @ W2; epilogue writes g_out = h2*dinv^2 + b2
__global__ void k_gemm2(const float* __restrict__ W2, const float* __restrict__ b2) {
    __shared__ float sW[128 * 64];
    const int c4 = (threadIdx.x & 15) * 4;
    const int rt = threadIdx.x >> 4;
    const size_t row0 = (size_t)blockIdx.x * 64 + rt * 4;

    const float4* Wv  = (const float4*)W2;
    float4*       sWv = (float4*)sW;
    #pragma unroll
    for (int i = threadIdx.x; i < 2048; i += 256) sWv[i] = Wv[i];
    __syncthreads();

    if (row0 >= NN) return;

    float4 acc[4];
    #pragma unroll
    for (int r = 0; r < 4; r++) acc[r] = make_float4(0.f, 0.f, 0.f, 0.f);

    #pragma unroll
    for (int k4 = 0; k4 < 32; k4++) {
        float4 xv[4];
        #pragma unroll
        for (int r = 0; r < 4; r++) {
            float4 v = *(const float4*)(g_a1 + (row0 + r) * 128 + k4 * 4);
            v.x = fmaxf(v.x, 0.f); v.y = fmaxf(v.y, 0.f);
            v.z = fmaxf(v.z, 0.f); v.w = fmaxf(v.w, 0.f);
            xv[r] = v;
        }
        #pragma unroll
        for (int kq = 0; kq < 4; kq++) {
            float4 w = *(const float4*)&sW[(k4 * 4 + kq) * 64 + c4];
            #pragma unroll
            for (int r = 0; r < 4; r++) {
                float xs = (kq == 0) ? xv[r].x : (kq == 1) ? xv[r].y
                         : (kq == 2) ? xv[r].z : xv[r].w;
                acc[r].x += xs * w.x;
                acc[r].y += xs * w.y;
                acc[r].z += xs * w.z;
                acc[r].w += xs * w.w;
            }
        }
    }

    float4 b = *(const float4*)(b2 + c4);
    #pragma unroll
    for (int r = 0; r < 4; r++) {
        size_t row = row0 + r;
        *(float4*)(g_h2 + row * 64 + c4) = acc[r];
        float di = g_dinv[row];
        float s  = di * di;
        float4 o = make_float4(acc[r].x * s + b.x, acc[r].y * s + b.y,
                               acc[r].z * s + b.z, acc[r].w * s + b.w);
        *(float4*)(g_out + row * 64 + c4) = o;
    }
}

// ---------------------------------------------------------------------------
// Layer-1 edge scatter: warp per edge, one float4 vector atomic per lane.
__global__ void k_scatter1(const int* __restrict__ ei) {
    int t = blockIdx.x * blockDim.x + threadIdx.x;
    int e = t >> 5;
    if (e >= EE) return;
    int j4 = (t & 31) * 4;
    int s = ei[e];
    int d = ei[EE + e];
    float w = g_norm[e];
    float4 v = *(const float4*)(g_h1 + (size_t)s * 128 + j4);
    v.x *= w; v.y *= w; v.z *= w; v.w *= w;
    atomicAdd((float4*)(g_a1 + (size_t)d * 128 + j4), v);
}

// Layer-2 edge scatter: 16 lanes per edge, one float4 vector atomic per lane.
__global__ void k_scatter2(const int* __restrict__ ei) {
    int t = blockIdx.x * blockDim.x + threadIdx.x;
    int e = t >> 4;
    if (e >= EE) return;
    int j4 = (t & 15) * 4;
    int s = ei[e];
    int d = ei[EE + e];
    float w = g_norm[e];
    float4 v = *(const float4*)(g_h2 + (size_t)s * 64 + j4);
    v.x *= w; v.y *= w; v.z *= w; v.w *= w;
    atomicAdd((float4*)(g_out + (size_t)d * 64 + j4), v);
}

// Final: plain coalesced stores into harness's d_out.
__global__ void k_copy_out(float* __restrict__ out) {
    size_t t = (size_t)blockIdx.x * blockDim.x + threadIdx.x;
    if (t >= (size_t)NN * 16) return;
    ((float4*)out)[t] = ((const float4*)g_out)[t];
}

// ---------------------------------------------------------------------------
extern "C" void kernel_launch(void* const* d_in, const int* in_sizes, int n_in,
                              void* d_out, int out_size) {
    const float* x  = (const float*)d_in[0];
    const int*   ei = (const int*)d_in[1];     // int32 (JAX x64 disabled)
    const float* W1 = (const float*)d_in[2];
    const float* b1 = (const float*)d_in[3];
    const float* W2 = (const float*)d_in[4];
    const float* b2 = (const float*)d_in[5];
    float* out = (float*)d_out;

    const int T = 256;

    // degrees + edge preprocessing (dinv must precede gemm1's fused epilogue)
    k_init_deg<<<(NN + T - 1) / T, T>>>();
    k_count<<<(EE + T - 1) / T, T>>>(ei);
    k_rsqrt<<<(NN + T - 1) / T, T>>>();
    k_norm<<<(EE + T - 1) / T, T>>>(ei);

    // layer 1
    k_gemm1<<<NN / 32, T>>>(x, W1, b1);                   // 100000 % 32 == 0
    k_scatter1<<<((size_t)EE * 32 + T - 1) / T, T>>>(ei);

    // layer 2
    k_gemm2<<<(NN + 63) / 64, T>>>(W2, b2);
    k_scatter2<<<((size_t)EE * 16 + T - 1) / T, T>>>(ei);
    k_copy_out<<<((size_t)NN * 16 + T - 1) / T, T>>>(out);
}

// round 6
// speedup vs baseline: 2.7439x; 1.5803x over previous
#include <cuda_runtime.h>
#include <cuda_bf16.h>
#include <cstdint>

// Problem constants (match reference_code)
#define NN   100000
#define C_IN  128
#define C_HID 128
#define C_OUT 64
#define EE   1600000
#define NBLK ((NN + 255) / 256)     // 391 scan blocks

// -------- device scratch (static allocation; no cudaMalloc allowed) --------
__device__ int   g_cnt[NN];                        // in-degree (excl self-loop)
__device__ float g_dinv[NN];                       // rsqrt(1+deg)
__device__ int   g_row[NN];                        // CSR row starts (exclusive scan)
__device__ int   g_cursor[NN];                     // fill cursors
__device__ int   g_bsum[NBLK];                     // scan block sums
__device__ int   g_boff[NBLK];                     // scanned block offsets
__device__ int   g_csr_src[EE];                    // src per dst-sorted edge
__device__ float g_csr_w[EE];                      // norm per dst-sorted edge
__device__ float g_h1[(size_t)NN * C_HID];         // x @ W1
__device__ float g_a1[(size_t)NN * C_HID];         // aggregated layer-1
__device__ float g_h2[(size_t)NN * C_OUT];         // relu(a1) @ W2

// ---------------------------------------------------------------------------
__global__ void k_zero_cnt() {
    int i = blockIdx.x * blockDim.x + threadIdx.x;
    if (i < NN) g_cnt[i] = 0;
}

__global__ void k_count(const int* __restrict__ ei) {
    int e = blockIdx.x * blockDim.x + threadIdx.x;
    if (e >= EE) return;
    atomicAdd(&g_cnt[ei[EE + e]], 1);
}

__global__ void k_dinv() {
    int i = blockIdx.x * blockDim.x + threadIdx.x;
    if (i < NN) g_dinv[i] = rsqrtf(1.0f + (float)g_cnt[i]);
}

// ---- 3-kernel exclusive scan of g_cnt -> g_row ----
__global__ void k_scan_block() {
    __shared__ int sdata[256];
    int i = blockIdx.x * 256 + threadIdx.x;
    int v = (i < NN) ? g_cnt[i] : 0;
    sdata[threadIdx.x] = v;
    __syncthreads();
    #pragma unroll
    for (int off = 1; off < 256; off <<= 1) {
        int t = (threadIdx.x >= off) ? sdata[threadIdx.x - off] : 0;
        __syncthreads();
        sdata[threadIdx.x] += t;
        __syncthreads();
    }
    if (i < NN) g_row[i] = sdata[threadIdx.x] - v;     // exclusive
    if (threadIdx.x == 255) g_bsum[blockIdx.x] = sdata[255];
}

__global__ void k_scan_bsums() {
    __shared__ int sdata[512];
    int v = (threadIdx.x < NBLK) ? g_bsum[threadIdx.x] : 0;
    sdata[threadIdx.x] = v;
    __syncthreads();
    #pragma unroll
    for (int off = 1; off < 512; off <<= 1) {
        int t = (threadIdx.x >= off) ? sdata[threadIdx.x - off] : 0;
        __syncthreads();
        sdata[threadIdx.x] += t;
        __syncthreads();
    }
    if (threadIdx.x < NBLK) g_boff[threadIdx.x] = sdata[threadIdx.x] - v;
}

__global__ void k_scan_add() {
    int i = blockIdx.x * 256 + threadIdx.x;
    if (i >= NN) return;
    int r = g_row[i] + g_boff[blockIdx.x];
    g_row[i] = r;
    g_cursor[i] = r;
}

// ---- reorder edges into CSR (dst-grouped), norm computed here ----
__global__ void k_reorder(const int* __restrict__ ei) {
    int e = blockIdx.x * blockDim.x + threadIdx.x;
    if (e >= EE) return;
    int s = ei[e];
    int d = ei[EE + e];
    int pos = atomicAdd(&g_cursor[d], 1);
    g_csr_src[pos] = s;
    g_csr_w[pos]   = g_dinv[s] * g_dinv[d];
}

// ---------------------------------------------------------------------------
// GEMM1: g_h1 = x @ W1
__global__ void k_gemm1(const float* __restrict__ A, const float* __restrict__ W) {
    __shared__ float sW[64 * 128];
    const int c4  = (threadIdx.x & 31) * 4;
    const int rt  = threadIdx.x >> 5;
    const size_t row0 = (size_t)blockIdx.x * 32 + rt * 4;

    float4 acc[4];
    #pragma unroll
    for (int r = 0; r < 4; r++) acc[r] = make_float4(0.f, 0.f, 0.f, 0.f);

    for (int kk = 0; kk < 128; kk += 64) {
        const float4* Wv  = (const float4*)(W + (size_t)kk * 128);
        float4*       sWv = (float4*)sW;
        #pragma unroll
        for (int i = threadIdx.x; i < 2048; i += 256) sWv[i] = Wv[i];
        __syncthreads();

        #pragma unroll
        for (int k4 = 0; k4 < 16; k4++) {
            float4 xv[4];
            #pragma unroll
            for (int r = 0; r < 4; r++)
                xv[r] = *(const float4*)(A + (row0 + r) * 128 + kk + k4 * 4);
            #pragma unroll
            for (int kq = 0; kq < 4; kq++) {
                float4 w = *(const float4*)&sW[(k4 * 4 + kq) * 128 + c4];
                #pragma unroll
                for (int r = 0; r < 4; r++) {
                    float xs = (kq == 0) ? xv[r].x : (kq == 1) ? xv[r].y
                             : (kq == 2) ? xv[r].z : xv[r].w;
                    acc[r].x += xs * w.x;
                    acc[r].y += xs * w.y;
                    acc[r].z += xs * w.z;
                    acc[r].w += xs * w.w;
                }
            }
        }
        __syncthreads();
    }
    #pragma unroll
    for (int r = 0; r < 4; r++)
        *(float4*)(g_h1 + (row0 + r) * 128 + c4) = acc[r];
}

// GEMM2: g_h2 = relu(g_a1) @ W2
__global__ void k_gemm2(const float* __restrict__ W2) {
    __shared__ float sW[128 * 64];
    const int c4 = (threadIdx.x & 15) * 4;
    const int rt = threadIdx.x >> 4;
    const size_t row0 = (size_t)blockIdx.x * 64 + rt * 4;

    const float4* Wv  = (const float4*)W2;
    float4*       sWv = (float4*)sW;
    #pragma unroll
    for (int i = threadIdx.x; i < 2048; i += 256) sWv[i] = Wv[i];
    __syncthreads();

    if (row0 >= NN) return;

    float4 acc[4];
    #pragma unroll
    for (int r = 0; r < 4; r++) acc[r] = make_float4(0.f, 0.f, 0.f, 0.f);

    #pragma unroll
    for (int k4 = 0; k4 < 32; k4++) {
        float4 xv[4];
        #pragma unroll
        for (int r = 0; r < 4; r++) {
            float4 v = *(const float4*)(g_a1 + (row0 + r) * 128 + k4 * 4);
            v.x = fmaxf(v.x, 0.f); v.y = fmaxf(v.y, 0.f);
            v.z = fmaxf(v.z, 0.f); v.w = fmaxf(v.w, 0.f);
            xv[r] = v;
        }
        #pragma unroll
        for (int kq = 0; kq < 4; kq++) {
            float4 w = *(const float4*)&sW[(k4 * 4 + kq) * 64 + c4];
            #pragma unroll
            for (int r = 0; r < 4; r++) {
                float xs = (kq == 0) ? xv[r].x : (kq == 1) ? xv[r].y
                         : (kq == 2) ? xv[r].z : xv[r].w;
                acc[r].x += xs * w.x;
                acc[r].y += xs * w.y;
                acc[r].z += xs * w.z;
                acc[r].w += xs * w.w;
            }
        }
    }
    #pragma unroll
    for (int r = 0; r < 4; r++)
        *(float4*)(g_h2 + (row0 + r) * 64 + c4) = acc[r];
}

// ---------------------------------------------------------------------------
// Layer-1 aggregation: warp per dst node, gather+FMA in registers, one store.
// acc starts at self-loop+bias: h1[i]*dinv^2 + b1.
__global__ void k_agg1(const float* __restrict__ b1) {
    int t = blockIdx.x * blockDim.x + threadIdx.x;
    int i = t >> 5;
    if (i >= NN) return;
    int j4 = (t & 31) * 4;

    float di = g_dinv[i];
    float ss = di * di;
    float4 h = *(const float4*)(g_h1 + (size_t)i * 128 + j4);
    float4 b = *(const float4*)(b1 + j4);
    float4 acc = make_float4(h.x * ss + b.x, h.y * ss + b.y,
                             h.z * ss + b.z, h.w * ss + b.w);

    int start = g_row[i];
    int end   = start + g_cnt[i];
    for (int k = start; k < end; k++) {
        int   s = g_csr_src[k];
        float w = g_csr_w[k];
        float4 v = *(const float4*)(g_h1 + (size_t)s * 128 + j4);
        acc.x += w * v.x;
        acc.y += w * v.y;
        acc.z += w * v.z;
        acc.w += w * v.w;
    }
    *(float4*)(g_a1 + (size_t)i * 128 + j4) = acc;
}

// Layer-2 aggregation: 16 lanes per node, writes straight into d_out.
__global__ void k_agg2(const float* __restrict__ b2, float* __restrict__ out) {
    int t = blockIdx.x * blockDim.x + threadIdx.x;
    int i = t >> 4;
    if (i >= NN) return;
    int j4 = (t & 15) * 4;

    float di = g_dinv[i];
    float ss = di * di;
    float4 h = *(const float4*)(g_h2 + (size_t)i * 64 + j4);
    float4 b = *(const float4*)(b2 + j4);
    float4 acc = make_float4(h.x * ss + b.x, h.y * ss + b.y,
                             h.z * ss + b.z, h.w * ss + b.w);

    int start = g_row[i];
    int end   = start + g_cnt[i];
    for (int k = start; k < end; k++) {
        int   s = g_csr_src[k];
        float w = g_csr_w[k];
        float4 v = *(const float4*)(g_h2 + (size_t)s * 64 + j4);
        acc.x += w * v.x;
        acc.y += w * v.y;
        acc.z += w * v.z;
        acc.w += w * v.w;
    }
    *(float4*)(out + (size_t)i * 64 + j4) = acc;
}

// ---------------------------------------------------------------------------
extern "C" void kernel_launch(void* const* d_in, const int* in_sizes, int n_in,
                              void* d_out, int out_size) {
    const float* x  = (const float*)d_in[0];
    const int*   ei = (const int*)d_in[1];     // int32 (JAX x64 disabled)
    const float* W1 = (const float*)d_in[2];
    const float* b1 = (const float*)d_in[3];
    const float* W2 = (const float*)d_in[4];
    const float* b2 = (const float*)d_in[5];
    float* out = (float*)d_out;

    const int T = 256;

    // degrees + dinv + CSR build
    k_zero_cnt<<<NBLK, T>>>();
    k_count<<<(EE + T - 1) / T, T>>>(ei);
    k_dinv<<<NBLK, T>>>();
    k_scan_block<<<NBLK, T>>>();
    k_scan_bsums<<<1, 512>>>();
    k_scan_add<<<NBLK, T>>>();
    k_reorder<<<(EE + T - 1) / T, T>>>(ei);

    // layer 1
    k_gemm1<<<NN / 32, T>>>(x, W1);                       // 100000 % 32 == 0
    k_agg1<<<((size_t)NN * 32 + T - 1) / T, T>>>(b1);

    // layer 2
    k_gemm2<<<(NN + 63) / 64, T>>>(W2);
    k_agg2<<<((size_t)NN * 16 + T - 1) / T, T>>>(b2, out);
}

// round 7
// speedup vs baseline: 2.8341x; 1.0329x over previous
#include <cuda_runtime.h>
#include <cuda_bf16.h>
#include <cstdint>

// Problem constants (match reference_code)
#define NN   100000
#define C_IN  128
#define C_HID 128
#define C_OUT 64
#define EE   1600000
#define NBLK ((NN + 255) / 256)     // 391 scan blocks

// -------- device scratch (static allocation; no cudaMalloc allowed) --------
__device__ int   g_cnt[NN];                        // in-degree (excl self-loop)
__device__ float g_dinv[NN];                       // rsqrt(1+deg)
__device__ int   g_row[NN];                        // CSR row starts (exclusive scan)
__device__ int   g_cursor[NN];                     // fill cursors
__device__ int   g_bsum[NBLK];                     // scan block sums
__device__ int   g_boff[NBLK];                     // scanned block offsets
__device__ int   g_csr_src[EE];                    // src per dst-sorted edge
__device__ float g_csr_w[EE];                      // norm per dst-sorted edge
__device__ float g_h1[(size_t)NN * C_HID];         // x @ W1
__device__ float g_a1[(size_t)NN * C_HID];         // aggregated layer-1
__device__ float g_h2[(size_t)NN * C_OUT];         // relu(a1) @ W2

// ---------------------------------------------------------------------------
__global__ void k_zero_cnt() {
    int i = blockIdx.x * blockDim.x + threadIdx.x;
    if (i < NN) g_cnt[i] = 0;
}

__global__ void k_count(const int* __restrict__ ei) {
    int e = blockIdx.x * blockDim.x + threadIdx.x;
    if (e >= EE) return;
    atomicAdd(&g_cnt[ei[EE + e]], 1);
}

__global__ void k_dinv() {
    int i = blockIdx.x * blockDim.x + threadIdx.x;
    if (i < NN) g_dinv[i] = rsqrtf(1.0f + (float)g_cnt[i]);
}

// ---- 3-kernel exclusive scan of g_cnt -> g_row ----
__global__ void k_scan_block() {
    __shared__ int sdata[256];
    int i = blockIdx.x * 256 + threadIdx.x;
    int v = (i < NN) ? g_cnt[i] : 0;
    sdata[threadIdx.x] = v;
    __syncthreads();
    #pragma unroll
    for (int off = 1; off < 256; off <<= 1) {
        int t = (threadIdx.x >= off) ? sdata[threadIdx.x - off] : 0;
        __syncthreads();
        sdata[threadIdx.x] += t;
        __syncthreads();
    }
    if (i < NN) g_row[i] = sdata[threadIdx.x] - v;     // exclusive
    if (threadIdx.x == 255) g_bsum[blockIdx.x] = sdata[255];
}

__global__ void k_scan_bsums() {
    __shared__ int sdata[512];
    int v = (threadIdx.x < NBLK) ? g_bsum[threadIdx.x] : 0;
    sdata[threadIdx.x] = v;
    __syncthreads();
    #pragma unroll
    for (int off = 1; off < 512; off <<= 1) {
        int t = (threadIdx.x >= off) ? sdata[threadIdx.x - off] : 0;
        __syncthreads();
        sdata[threadIdx.x] += t;
        __syncthreads();
    }
    if (threadIdx.x < NBLK) g_boff[threadIdx.x] = sdata[threadIdx.x] - v;
}

__global__ void k_scan_add() {
    int i = blockIdx.x * 256 + threadIdx.x;
    if (i >= NN) return;
    int r = g_row[i] + g_boff[blockIdx.x];
    g_row[i] = r;
    g_cursor[i] = r;
}

// ---- reorder edges into CSR (dst-grouped), norm computed here ----
__global__ void k_reorder(const int* __restrict__ ei) {
    int e = blockIdx.x * blockDim.x + threadIdx.x;
    if (e >= EE) return;
    int s = ei[e];
    int d = ei[EE + e];
    int pos = atomicAdd(&g_cursor[d], 1);
    g_csr_src[pos] = s;
    g_csr_w[pos]   = g_dinv[s] * g_dinv[d];
}

// ---------------------------------------------------------------------------
// GEMM1: g_h1[N,128] = x[N,128] @ W1[128,128]
// 256 thr/block, 64 rows x 128 cols per block. Thread: 8 rows x 4 cols.
// A loads double-buffered in registers to hide L2 latency.
__global__ void __launch_bounds__(256) k_gemm1(const float* __restrict__ A,
                                               const float* __restrict__ W) {
    __shared__ float sW[64 * 128];                 // 32KB chunk of W
    const int c4  = (threadIdx.x & 31) * 4;
    const int rt  = threadIdx.x >> 5;              // 8 row-threads
    const int row0 = blockIdx.x * 64 + rt * 8;     // 8 rows per thread

    // clamped row indices for tail block (loads safe, stores guarded)
    int rr[8];
    #pragma unroll
    for (int r = 0; r < 8; r++) {
        int ri = row0 + r;
        rr[r] = (ri < NN) ? ri : (NN - 1);
    }

    float4 acc[8];
    #pragma unroll
    for (int r = 0; r < 8; r++) acc[r] = make_float4(0.f, 0.f, 0.f, 0.f);

    float4 abuf[2][8];

    for (int kk = 0; kk < 128; kk += 64) {
        const float4* Wv  = (const float4*)(W + (size_t)kk * 128);
        float4*       sWv = (float4*)sW;
        #pragma unroll
        for (int i = threadIdx.x; i < 2048; i += 256) sWv[i] = Wv[i];
        __syncthreads();

        // prime pipeline: k4 = 0
        #pragma unroll
        for (int r = 0; r < 8; r++)
            abuf[0][r] = *(const float4*)(A + (size_t)rr[r] * 128 + kk);

        #pragma unroll
        for (int k4 = 0; k4 < 16; k4++) {
            const int cur = k4 & 1;
            if (k4 < 15) {
                #pragma unroll
                for (int r = 0; r < 8; r++)
                    abuf[cur ^ 1][r] = *(const float4*)(A + (size_t)rr[r] * 128 + kk + (k4 + 1) * 4);
            }
            #pragma unroll
            for (int kq = 0; kq < 4; kq++) {
                float4 w = *(const float4*)&sW[(k4 * 4 + kq) * 128 + c4];
                #pragma unroll
                for (int r = 0; r < 8; r++) {
                    float xs = (kq == 0) ? abuf[cur][r].x : (kq == 1) ? abuf[cur][r].y
                             : (kq == 2) ? abuf[cur][r].z : abuf[cur][r].w;
                    acc[r].x += xs * w.x;
                    acc[r].y += xs * w.y;
                    acc[r].z += xs * w.z;
                    acc[r].w += xs * w.w;
                }
            }
        }
        __syncthreads();
    }

    #pragma unroll
    for (int r = 0; r < 8; r++) {
        int ri = row0 + r;
        if (ri < NN)
            *(float4*)(g_h1 + (size_t)ri * 128 + c4) = acc[r];
    }
}

// GEMM2: g_h2[N,64] = relu(g_a1)[N,128] @ W2[128,64]
// 256 thr/block, 64 rows x 64 cols. Thread: 4 rows x 4 cols, pipelined A loads.
__global__ void __launch_bounds__(256) k_gemm2(const float* __restrict__ W2) {
    __shared__ float sW[128 * 64];                 // full W2, 32KB
    const int c4 = (threadIdx.x & 15) * 4;
    const int rt = threadIdx.x >> 4;               // 16 row-threads
    const int row0 = blockIdx.x * 64 + rt * 4;     // 4 rows per thread

    const float4* Wv  = (const float4*)W2;
    float4*       sWv = (float4*)sW;
    #pragma unroll
    for (int i = threadIdx.x; i < 2048; i += 256) sWv[i] = Wv[i];
    __syncthreads();

    int rr[4];
    #pragma unroll
    for (int r = 0; r < 4; r++) {
        int ri = row0 + r;
        rr[r] = (ri < NN) ? ri : (NN - 1);
    }

    float4 acc[4];
    #pragma unroll
    for (int r = 0; r < 4; r++) acc[r] = make_float4(0.f, 0.f, 0.f, 0.f);

    float4 abuf[2][4];
    #pragma unroll
    for (int r = 0; r < 4; r++)
        abuf[0][r] = *(const float4*)(g_a1 + (size_t)rr[r] * 128);

    #pragma unroll
    for (int k4 = 0; k4 < 32; k4++) {
        const int cur = k4 & 1;
        if (k4 < 31) {
            #pragma unroll
            for (int r = 0; r < 4; r++)
                abuf[cur ^ 1][r] = *(const float4*)(g_a1 + (size_t)rr[r] * 128 + (k4 + 1) * 4);
        }
        // relu on the staged values
        float4 xv[4];
        #pragma unroll
        for (int r = 0; r < 4; r++) {
            xv[r].x = fmaxf(abuf[cur][r].x, 0.f);
            xv[r].y = fmaxf(abuf[cur][r].y, 0.f);
            xv[r].z = fmaxf(abuf[cur][r].z, 0.f);
            xv[r].w = fmaxf(abuf[cur][r].w, 0.f);
        }
        #pragma unroll
        for (int kq = 0; kq < 4; kq++) {
            float4 w = *(const float4*)&sW[(k4 * 4 + kq) * 64 + c4];
            #pragma unroll
            for (int r = 0; r < 4; r++) {
                float xs = (kq == 0) ? xv[r].x : (kq == 1) ? xv[r].y
                         : (kq == 2) ? xv[r].z : xv[r].w;
                acc[r].x += xs * w.x;
                acc[r].y += xs * w.y;
                acc[r].z += xs * w.z;
                acc[r].w += xs * w.w;
            }
        }
    }

    #pragma unroll
    for (int r = 0; r < 4; r++) {
        int ri = row0 + r;
        if (ri < NN)
            *(float4*)(g_h2 + (size_t)ri * 64 + c4) = acc[r];
    }
}

// ---------------------------------------------------------------------------
// Layer-1 aggregation: warp per dst node, gather+FMA in registers, one store.
__global__ void k_agg1(const float* __restrict__ b1) {
    int t = blockIdx.x * blockDim.x + threadIdx.x;
    int i = t >> 5;
    if (i >= NN) return;
    int j4 = (t & 31) * 4;

    float di = g_dinv[i];
    float ss = di * di;
    float4 h = *(const float4*)(g_h1 + (size_t)i * 128 + j4);
    float4 b = *(const float4*)(b1 + j4);
    float4 acc = make_float4(h.x * ss + b.x, h.y * ss + b.y,
                             h.z * ss + b.z, h.w * ss + b.w);

    int start = g_row[i];
    int end   = start + g_cnt[i];
    for (int k = start; k < end; k++) {
        int   s = g_csr_src[k];
        float w = g_csr_w[k];
        float4 v = *(const float4*)(g_h1 + (size_t)s * 128 + j4);
        acc.x += w * v.x;
        acc.y += w * v.y;
        acc.z += w * v.z;
        acc.w += w * v.w;
    }
    *(float4*)(g_a1 + (size_t)i * 128 + j4) = acc;
}

// Layer-2 aggregation: 16 lanes per node, writes straight into d_out.
__global__ void k_agg2(const float* __restrict__ b2, float* __restrict__ out) {
    int t = blockIdx.x * blockDim.x + threadIdx.x;
    int i = t >> 4;
    if (i >= NN) return;
    int j4 = (t & 15) * 4;

    float di = g_dinv[i];
    float ss = di * di;
    float4 h = *(const float4*)(g_h2 + (size_t)i * 64 + j4);
    float4 b = *(const float4*)(b2 + j4);
    float4 acc = make_float4(h.x * ss + b.x, h.y * ss + b.y,
                             h.z * ss + b.z, h.w * ss + b.w);

    int start = g_row[i];
    int end   = start + g_cnt[i];
    for (int k = start; k < end; k++) {
        int   s = g_csr_src[k];
        float w = g_csr_w[k];
        float4 v = *(const float4*)(g_h2 + (size_t)s * 64 + j4);
        acc.x += w * v.x;
        acc.y += w * v.y;
        acc.z += w * v.z;
        acc.w += w * v.w;
    }
    *(float4*)(out + (size_t)i * 64 + j4) = acc;
}

// ---------------------------------------------------------------------------
extern "C" void kernel_launch(void* const* d_in, const int* in_sizes, int n_in,
                              void* d_out, int out_size) {
    const float* x  = (const float*)d_in[0];
    const int*   ei = (const int*)d_in[1];     // int32 (JAX x64 disabled)
    const float* W1 = (const float*)d_in[2];
    const float* b1 = (const float*)d_in[3];
    const float* W2 = (const float*)d_in[4];
    const float* b2 = (const float*)d_in[5];
    float* out = (float*)d_out;

    const int T = 256;

    // degrees + dinv + CSR build
    k_zero_cnt<<<NBLK, T>>>();
    k_count<<<(EE + T - 1) / T, T>>>(ei);
    k_dinv<<<NBLK, T>>>();
    k_scan_block<<<NBLK, T>>>();
    k_scan_bsums<<<1, 512>>>();
    k_scan_add<<<NBLK, T>>>();
    k_reorder<<<(EE + T - 1) / T, T>>>(ei);

    // layer 1
    k_gemm1<<<(NN + 63) / 64, T>>>(x, W1);
    k_agg1<<<((size_t)NN * 32 + T - 1) / T, T>>>(b1);

    // layer 2
    k_gemm2<<<(NN + 63) / 64, T>>>(W2);
    k_agg2<<<((size_t)NN * 16 + T - 1) / T, T>>>(b2, out);
}